// round 14
// baseline (speedup 1.0000x reference)
#include <cuda_runtime.h>
#include <cstdint>

// Problem constants
#define NTOK   49
#define CDIM   128
#define NHEAD  4
#define NWIN   64
#define NWB    8192
#define QSCALE 0.17677669529663687f   // (128/4)^-0.5

// Shared-memory strides (floats). All ≡ 4 (mod 32) -> conflict-free mma fragment loads.
#define XS 132        // X / O tile stride      (64 rows)
#define QS 388        // QKV tile stride        (64 rows x 384 cols)
#define PS 68         // P (softmax) stride     (4*64 rows x 64 cols)
#define SMEM_FLOATS (64*XS + 64*QS + 4*64*PS)
#define SMEM_BYTES  (SMEM_FLOATS * 4)

// Scratch (device globals: allocation-free per harness rules)
__device__ float d_bm[NWIN * NHEAD * 64 * 64];   // combined mask+bias, padded, 16 MB
__device__ float d_wqkv[384 * 128];              // tf32-rounded qkv_w
__device__ float d_wproj[128 * 128];             // tf32-rounded proj_w

__device__ __forceinline__ float tf32f(float x) {
    unsigned u;
    asm("cvt.rna.tf32.f32 %0, %1;" : "=r"(u) : "f"(x));
    return __uint_as_float(u);
}

__device__ __forceinline__ void mma8(float (&c)[4], const unsigned (&a)[4], const unsigned (&b)[2]) {
    asm volatile(
        "mma.sync.aligned.m16n8k8.row.col.f32.tf32.tf32.f32 "
        "{%0,%1,%2,%3}, {%4,%5,%6,%7}, {%8,%9}, {%0,%1,%2,%3};"
        : "+f"(c[0]), "+f"(c[1]), "+f"(c[2]), "+f"(c[3])
        : "r"(a[0]), "r"(a[1]), "r"(a[2]), "r"(a[3]), "r"(b[0]), "r"(b[1]));
}

// ---------------------------------------------------------------------------
// Prep: combined bias+mask tensor (padded to 64x64 with -1e30) + tf32 weights
// ---------------------------------------------------------------------------
__global__ void prep_kernel(const float* __restrict__ mask,
                            const float* __restrict__ qkv_w,
                            const float* __restrict__ proj_w,
                            const float* __restrict__ bias_table,
                            const int*   __restrict__ rel_index) {
    int idx = blockIdx.x * 256 + threadIdx.x;   // 0 .. 1048575
    if (idx < 384 * 128) d_wqkv[idx] = tf32f(qkv_w[idx]);
    if (idx < 128 * 128) d_wproj[idx] = tf32f(proj_w[idx]);

    int j = idx & 63;
    int i = (idx >> 6) & 63;
    int h = (idx >> 12) & 3;
    int w = idx >> 14;
    float v = -1e30f;
    if (i < NTOK && j < NTOK)
        v = mask[w * NTOK * NTOK + i * NTOK + j]
          + bias_table[rel_index[i * NTOK + j] * NHEAD + h];
    d_bm[idx] = v;
}

// ---------------------------------------------------------------------------
// Fused window attention: one block per window, 256 threads (8 warps)
// ---------------------------------------------------------------------------
extern __shared__ float sm[];

__global__ void __launch_bounds__(256, 1)
win_attn_kernel(const float* __restrict__ x,
                const float* __restrict__ qkv_b,
                const float* __restrict__ proj_b,
                float* __restrict__ out) {
    float* xs  = sm;                 // [64][XS]  X tile, later O tile (tf32 vals)
    float* qks = sm + 64 * XS;       // [64][QS]  Q|K|V  (tf32 vals, Q pre-scaled)
    float* sP  = qks + 64 * QS;      // [4][64][PS]  softmax probs (tf32 vals)

    const int tid  = threadIdx.x;
    const int lane = tid & 31;
    const int wid  = tid >> 5;
    const int g    = lane >> 2;      // groupID
    const int tg   = lane & 3;       // thread-in-group
    const int w    = blockIdx.x;
    const int win  = w & (NWIN - 1);

    // ---- Phase 0: load X (49x128, zero-pad to 64 rows), convert to tf32 ----
    {
        const float4* x4 = (const float4*)(x + (size_t)w * NTOK * CDIM);
        for (int i = tid; i < 64 * 32; i += 256) {
            int r = i >> 5, c4 = i & 31;
            float4 v = (r < NTOK) ? x4[r * 32 + c4] : make_float4(0.f, 0.f, 0.f, 0.f);
            v.x = tf32f(v.x); v.y = tf32f(v.y); v.z = tf32f(v.z); v.w = tf32f(v.w);
            *(float4*)(xs + r * XS + c4 * 4) = v;
        }
    }
    __syncthreads();

    // ---- Phase 1: QKV GEMM [64,128]@W^T[128,384]. Warp: rows 0..63, cols wid*48..+48
    {
        float acc[4][6][4];
        #pragma unroll
        for (int mt = 0; mt < 4; mt++)
            #pragma unroll
            for (int nt = 0; nt < 6; nt++)
                #pragma unroll
                for (int e = 0; e < 4; e++) acc[mt][nt][e] = 0.f;

        #pragma unroll 2
        for (int kb = 0; kb < 128; kb += 8) {
            unsigned bF[6][2];
            #pragma unroll
            for (int nt = 0; nt < 6; nt++) {
                const float* wp = d_wqkv + (wid * 48 + nt * 8 + g) * 128 + kb + tg;
                bF[nt][0] = __float_as_uint(wp[0]);
                bF[nt][1] = __float_as_uint(wp[4]);
            }
            #pragma unroll
            for (int mt = 0; mt < 4; mt++) {
                unsigned aF[4];
                const float* ap = xs + (mt * 16 + g) * XS + kb + tg;
                aF[0] = __float_as_uint(ap[0]);
                aF[1] = __float_as_uint(ap[8 * XS]);
                aF[2] = __float_as_uint(ap[4]);
                aF[3] = __float_as_uint(ap[8 * XS + 4]);
                #pragma unroll
                for (int nt = 0; nt < 6; nt++) mma8(acc[mt][nt], aF, bF[nt]);
            }
        }
        // Epilogue: +bias, scale Q columns, tf32-round, store to qks
        #pragma unroll
        for (int nt = 0; nt < 6; nt++) {
            int c = wid * 48 + nt * 8 + 2 * tg;
            float2 qb = *(const float2*)(qkv_b + c);
            float s = (c < 128) ? QSCALE : 1.0f;   // c,c+1 on same side of 128 (c even)
            #pragma unroll
            for (int mt = 0; mt < 4; mt++) {
                int r = mt * 16 + g;
                float2 v0, v1;
                v0.x = tf32f((acc[mt][nt][0] + qb.x) * s);
                v0.y = tf32f((acc[mt][nt][1] + qb.y) * s);
                v1.x = tf32f((acc[mt][nt][2] + qb.x) * s);
                v1.y = tf32f((acc[mt][nt][3] + qb.y) * s);
                *(float2*)(qks + r * QS + c)       = v0;
                *(float2*)(qks + (r + 8) * QS + c) = v1;
            }
        }
    }
    __syncthreads();

    // ---- Phase 2: per-head QK^T + bias/mask + register softmax + AV ----
    // Warp -> (head = wid/2, row half = wid&1): owns 32 full rows -> no cross-warp sync.
    {
        const int h  = wid >> 1;
        const int mh = wid & 1;

        float acc[2][8][4];
        #pragma unroll
        for (int mt = 0; mt < 2; mt++)
            #pragma unroll
            for (int nt = 0; nt < 8; nt++)
                #pragma unroll
                for (int e = 0; e < 4; e++) acc[mt][nt][e] = 0.f;

        #pragma unroll
        for (int kb = 0; kb < 32; kb += 8) {
            unsigned bF[8][2];
            #pragma unroll
            for (int nt = 0; nt < 8; nt++) {
                const float* kp = qks + (nt * 8 + g) * QS + 128 + h * 32 + kb + tg;
                bF[nt][0] = __float_as_uint(kp[0]);
                bF[nt][1] = __float_as_uint(kp[4]);
            }
            #pragma unroll
            for (int mt = 0; mt < 2; mt++) {
                unsigned aF[4];
                const float* ap = qks + (mh * 32 + mt * 16 + g) * QS + h * 32 + kb + tg;
                aF[0] = __float_as_uint(ap[0]);
                aF[1] = __float_as_uint(ap[8 * QS]);
                aF[2] = __float_as_uint(ap[4]);
                aF[3] = __float_as_uint(ap[8 * QS + 4]);
                #pragma unroll
                for (int nt = 0; nt < 8; nt++) mma8(acc[mt][nt], aF, bF[nt]);
            }
        }

        // Add precomputed bias+mask (pad slots are -1e30 -> auto-mask)
        const float* bmw = d_bm + ((size_t)(win * NHEAD + h) * 64 + mh * 32) * 64;
        #pragma unroll
        for (int mt = 0; mt < 2; mt++) {
            int r = mt * 16 + g;
            #pragma unroll
            for (int nt = 0; nt < 8; nt++) {
                int c = nt * 8 + 2 * tg;
                float2 b0 = *(const float2*)(bmw + r * 64 + c);
                float2 b1 = *(const float2*)(bmw + (r + 8) * 64 + c);
                acc[mt][nt][0] += b0.x; acc[mt][nt][1] += b0.y;
                acc[mt][nt][2] += b1.x; acc[mt][nt][3] += b1.y;
            }
        }

        // Register softmax: each thread holds 16 values per row-group, quad-shfl reduce
        #pragma unroll
        for (int rg = 0; rg < 4; rg++) {
            const int mt = rg >> 1, e0 = (rg & 1) * 2;
            float mx = -1e30f;
            #pragma unroll
            for (int nt = 0; nt < 8; nt++)
                mx = fmaxf(mx, fmaxf(acc[mt][nt][e0], acc[mt][nt][e0 + 1]));
            mx = fmaxf(mx, __shfl_xor_sync(0xffffffffu, mx, 1));
            mx = fmaxf(mx, __shfl_xor_sync(0xffffffffu, mx, 2));
            float sum = 0.f;
            #pragma unroll
            for (int nt = 0; nt < 8; nt++) {
                float ea = __expf(acc[mt][nt][e0]     - mx);
                float eb = __expf(acc[mt][nt][e0 + 1] - mx);
                acc[mt][nt][e0] = ea; acc[mt][nt][e0 + 1] = eb;
                sum += ea + eb;
            }
            sum += __shfl_xor_sync(0xffffffffu, sum, 1);
            sum += __shfl_xor_sync(0xffffffffu, sum, 2);
            float inv = __fdividef(1.0f, sum);
            int r = mh * 32 + mt * 16 + (rg & 1) * 8 + g;
            float* pr = sP + (h * 64 + r) * PS;
            #pragma unroll
            for (int nt = 0; nt < 8; nt++) {
                float2 pv;
                pv.x = tf32f(acc[mt][nt][e0] * inv);
                pv.y = tf32f(acc[mt][nt][e0 + 1] * inv);
                *(float2*)(pr + nt * 8 + 2 * tg) = pv;
            }
        }
        __syncwarp();

        // AV: O_h[32,32] = P_h[32,64] @ V_h[64,32]
        float oac[2][4][4];
        #pragma unroll
        for (int mt = 0; mt < 2; mt++)
            #pragma unroll
            for (int nt = 0; nt < 4; nt++)
                #pragma unroll
                for (int e = 0; e < 4; e++) oac[mt][nt][e] = 0.f;

        #pragma unroll
        for (int kb = 0; kb < 64; kb += 8) {
            unsigned bF[4][2];
            #pragma unroll
            for (int nt = 0; nt < 4; nt++) {
                const float* vp = qks + (kb + tg) * QS + 256 + h * 32 + nt * 8 + g;
                bF[nt][0] = __float_as_uint(vp[0]);
                bF[nt][1] = __float_as_uint(vp[4 * QS]);
            }
            #pragma unroll
            for (int mt = 0; mt < 2; mt++) {
                unsigned aF[4];
                const float* pp = sP + (h * 64 + mh * 32 + mt * 16 + g) * PS + kb + tg;
                aF[0] = __float_as_uint(pp[0]);
                aF[1] = __float_as_uint(pp[8 * PS]);
                aF[2] = __float_as_uint(pp[4]);
                aF[3] = __float_as_uint(pp[8 * PS + 4]);
                #pragma unroll
                for (int nt = 0; nt < 4; nt++) mma8(oac[mt][nt], aF, bF[nt]);
            }
        }
        // Write O into xs region (X no longer needed past the phase-1 barrier)
        #pragma unroll
        for (int nt = 0; nt < 4; nt++) {
            int c = h * 32 + nt * 8 + 2 * tg;
            #pragma unroll
            for (int mt = 0; mt < 2; mt++) {
                int r = mh * 32 + mt * 16 + g;
                float2 v0, v1;
                v0.x = tf32f(oac[mt][nt][0]); v0.y = tf32f(oac[mt][nt][1]);
                v1.x = tf32f(oac[mt][nt][2]); v1.y = tf32f(oac[mt][nt][3]);
                *(float2*)(xs + r * XS + c)       = v0;
                *(float2*)(xs + (r + 8) * XS + c) = v1;
            }
        }
    }
    __syncthreads();

    // ---- Phase 3: output proj [64,128]@Wp^T[128,128] + bias, store rows < 49 ----
    {
        float acc[4][2][4];
        #pragma unroll
        for (int mt = 0; mt < 4; mt++)
            #pragma unroll
            for (int nt = 0; nt < 2; nt++)
                #pragma unroll
                for (int e = 0; e < 4; e++) acc[mt][nt][e] = 0.f;

        #pragma unroll 4
        for (int kb = 0; kb < 128; kb += 8) {
            unsigned bF[2][2];
            #pragma unroll
            for (int nt = 0; nt < 2; nt++) {
                const float* wp = d_wproj + (wid * 16 + nt * 8 + g) * 128 + kb + tg;
                bF[nt][0] = __float_as_uint(wp[0]);
                bF[nt][1] = __float_as_uint(wp[4]);
            }
            #pragma unroll
            for (int mt = 0; mt < 4; mt++) {
                unsigned aF[4];
                const float* ap = xs + (mt * 16 + g) * XS + kb + tg;
                aF[0] = __float_as_uint(ap[0]);
                aF[1] = __float_as_uint(ap[8 * XS]);
                aF[2] = __float_as_uint(ap[4]);
                aF[3] = __float_as_uint(ap[8 * XS + 4]);
                #pragma unroll
                for (int nt = 0; nt < 2; nt++) mma8(acc[mt][nt], aF, bF[nt]);
            }
        }

        float* ob = out + (size_t)w * NTOK * CDIM;
        #pragma unroll
        for (int nt = 0; nt < 2; nt++) {
            int c = wid * 16 + nt * 8 + 2 * tg;
            float2 pb = *(const float2*)(proj_b + c);
            #pragma unroll
            for (int mt = 0; mt < 4; mt++) {
                int r = mt * 16 + g;
                if (r < NTOK) {
                    float2 v; v.x = acc[mt][nt][0] + pb.x; v.y = acc[mt][nt][1] + pb.y;
                    *(float2*)(ob + r * CDIM + c) = v;
                }
                if (r + 8 < NTOK) {
                    float2 v; v.x = acc[mt][nt][2] + pb.x; v.y = acc[mt][nt][3] + pb.y;
                    *(float2*)(ob + (r + 8) * CDIM + c) = v;
                }
            }
        }
    }
}

// ---------------------------------------------------------------------------
extern "C" void kernel_launch(void* const* d_in, const int* in_sizes, int n_in,
                              void* d_out, int out_size) {
    (void)in_sizes; (void)n_in; (void)out_size;
    const float* x          = (const float*)d_in[0];
    const float* mask       = (const float*)d_in[1];
    const float* qkv_w      = (const float*)d_in[2];
    const float* qkv_b      = (const float*)d_in[3];
    const float* proj_w     = (const float*)d_in[4];
    const float* proj_b     = (const float*)d_in[5];
    const float* bias_table = (const float*)d_in[6];
    const int*   rel_index  = (const int*)d_in[7];

    cudaFuncSetAttribute(win_attn_kernel,
                         cudaFuncAttributeMaxDynamicSharedMemorySize, SMEM_BYTES);

    prep_kernel<<<4096, 256>>>(mask, qkv_w, proj_w, bias_table, rel_index);
    win_attn_kernel<<<NWB, 256, SMEM_BYTES>>>(x, qkv_b, proj_b, (float*)d_out);
}